// round 2
// baseline (speedup 1.0000x reference)
#include <cuda_runtime.h>
#include <math.h>

#define KNB 40
#define DF 128
#define MDIM 384
#define C2 768
#define HH 4
#define DHD 96
#define BB 128
#define N1Q 10240
#define N2Q 256
#define THREADS 320
#define MC 8
#define KVP 772

// ---------------- scratch (__device__ globals, no allocation) ----------------
__device__ float g_WA[2][2][128 * 768];   // fused Wrel@[Wk|Wv] per layer/etype
__device__ float g_WB[2][128 * 768];      // [Wk|Wv] rows 128..255 (edge feat)
__device__ float g_WC[2][128 * 768];      // [Wk|Wv] rows 256..383 (time feat)
__device__ float g_qconst[2][384];
__device__ float g_WoM1[2][384 * 128];    // Wo @ Wm1[:384]
__device__ float g_h1[N1Q * DF];
__device__ float g_h2[N2Q * DF];

// cos with explicit range reduction (args up to ~2000 rad)
__device__ __forceinline__ float fcosr(float x) {
    float n = rintf(x * 0.15915494309189535f);
    float r = fmaf(n, -6.2831855f, x);       // hi part of 2*pi
    r = fmaf(n, 1.7484556e-7f, r);           // lo correction
    return __cosf(r);
}

__device__ __forceinline__ void fma4(float* a, float x, float4 v) {
    a[0] = fmaf(x, v.x, a[0]);
    a[1] = fmaf(x, v.y, a[1]);
    a[2] = fmaf(x, v.z, a[2]);
    a[3] = fmaf(x, v.w, a[3]);
}

// ---------------- precompute: fused K/V weights ----------------
__global__ void pre_weights(const float* __restrict__ Wrel,
                            const float* __restrict__ Wk,
                            const float* __restrict__ Wv) {
    int bid = blockIdx.x;          // 1024 = 2 layers * 4 mats * 128 rows
    int l = bid >> 9;
    int rem = bid & 511;
    int which = rem >> 7;          // 0:WA et0, 1:WA et1, 2:WB, 3:WC
    int m = rem & 127;
    int tid = threadIdx.x;         // 256
    const float* WkL = Wk + l * MDIM * MDIM;
    const float* WvL = Wv + l * MDIM * MDIM;
    if (which < 2) {
        const float* wr = Wrel + ((l * 2 + which) * 128 + m) * 128;
        float* out = &g_WA[l][which][m * C2];
        for (int c = tid; c < C2; c += 256) {
            const float* wsrc = (c < 384) ? (WkL + c) : (WvL + (c - 384));
            float acc = 0.f;
            for (int j = 0; j < 128; j++) acc = fmaf(wr[j], wsrc[j * MDIM], acc);
            out[c] = acc;
        }
    } else {
        int roff = (which == 2) ? 128 : 256;
        float* out = (which == 2) ? &g_WB[l][m * C2] : &g_WC[l][m * C2];
        for (int c = tid; c < C2; c += 256) {
            out[c] = (c < 384) ? WkL[(roff + m) * MDIM + c]
                               : WvL[(roff + m) * MDIM + (c - 384)];
        }
    }
}

// ---------------- precompute: qconst + Wo@Wm1 ----------------
__global__ void pre_misc(const float* __restrict__ Wq,
                         const float* __restrict__ Wo,
                         const float* __restrict__ Wm1,
                         const float* __restrict__ phase) {
    int bid = blockIdx.x;          // 770 = 2*(384+1)
    int l = bid / 385;
    int r = bid % 385;
    int tid = threadIdx.x;         // 384
    if (r == 384) {
        if (tid < 384) {
            float acc = 0.f;
            for (int j = 0; j < 128; j++)
                acc = fmaf(cosf(phase[j]), Wq[l * MDIM * MDIM + (256 + j) * MDIM + tid], acc);
            g_qconst[l][tid] = acc;
        }
    } else {
        if (tid < 128) {
            float acc = 0.f;
            for (int j = 0; j < MDIM; j++)
                acc = fmaf(Wo[l * MDIM * MDIM + r * MDIM + j],
                           Wm1[(l * 512 + j) * 128 + tid], acc);
            g_WoM1[l][r * 128 + tid] = acc;
        }
    }
}

// ---------------- fused attention layer: one CTA per query node ----------------
__global__ __launch_bounds__(THREADS, 1)
void attn_kernel(int layer,
                 const int* __restrict__ nghNode, const int* __restrict__ nghEidx,
                 const float* __restrict__ nghT, const int* __restrict__ nghEt,
                 const int* __restrict__ srcA, const int* __restrict__ srcB,
                 const float* __restrict__ srcTime,
                 const float* __restrict__ n_feat, const float* __restrict__ e_feat,
                 const float* __restrict__ mem_tab,
                 const float* __restrict__ freq, const float* __restrict__ phase,
                 const float* __restrict__ Wq, const float* __restrict__ Wm1,
                 const float* __restrict__ bm1, const float* __restrict__ Wm2,
                 const float* __restrict__ bm2) {
    extern __shared__ float sm[];
    float* sSRC = sm;                 // 128
    float* sQ   = sm + 128;           // 384
    float* sS   = sm + 512;           // 160
    float* sO   = sm + 672;           // 384
    float* sR   = sm + 1056;          // 128
    int*   sRawEt  = (int*)(sm + 1184);
    int*   sRawNid = (int*)(sm + 1224);
    int*   sRawEid = (int*)(sm + 1264);
    float* sRawT   = sm + 1304;
    int*   sEt   = (int*)(sm + 1344);
    int*   sMask = (int*)(sm + 1384);
    int*   sNid  = (int*)(sm + 1424);
    int*   sEid  = (int*)(sm + 1464);
    float* sDt   = sm + 1504;
    int*   sPerm = (int*)(sm + 1544); // -> 1584
    float* sNF  = sm + 1600;          // 40*128
    float* sEF  = sNF + KNB * DF;
    float* sTF  = sEF + KNB * DF;
    float* sWS  = sm + 1600 + 3 * KNB * DF;   // 4*MC*768
    float* sKVH = sm + 1600;          // 40*772 (overlays NF/EF/TF + part of WS)

    const int n = blockIdx.x;
    const int tid = threadIdx.x;

    // ---- P0: meta + src feature ----
    if (tid < KNB) {
        sRawNid[tid] = nghNode[n * KNB + tid];
        sRawEid[tid] = nghEidx[n * KNB + tid];
        sRawT[tid]   = nghT[n * KNB + tid];
        sRawEt[tid]  = nghEt[n * KNB + tid];
    }
    int srcId;
    float srcT;
    if (layer == 0) { srcId = srcA[n]; srcT = srcTime[n]; }
    else { srcId = (n < BB) ? srcA[n] : srcB[n - BB]; srcT = srcTime[n & (BB - 1)]; }
    if (tid < DF) sSRC[tid] = n_feat[srcId * DF + tid] + mem_tab[srcId * DF + tid];
    __syncthreads();
    if (tid == 0) {   // stable partition by etype -> warp-uniform A matrix
        int c = 0;
        for (int k = 0; k < KNB; k++) if (sRawEt[k] == 0) sPerm[c++] = k;
        for (int k = 0; k < KNB; k++) if (sRawEt[k] != 0) sPerm[c++] = k;
    }
    __syncthreads();
    if (tid < KNB) {
        int k = sPerm[tid];
        sEt[tid]   = sRawEt[k];
        sNid[tid]  = sRawNid[k];
        sEid[tid]  = sRawEid[k];
        sDt[tid]   = srcT - sRawT[k];
        sMask[tid] = (sRawNid[k] == 0) ? 1 : 0;
    }
    __syncthreads();

    // ---- Pq: q projection (src part + qconst) ----
    for (int c = tid; c < MDIM; c += THREADS) {
        float acc = g_qconst[layer][c];
        const float* wq = Wq + layer * MDIM * MDIM + c;
        for (int m = 0; m < DF; m++) acc = fmaf(sSRC[m], wq[m * MDIM], acc);
        sQ[c] = acc;
    }

    // ---- P1: stage neighbor features (sorted order) ----
    for (int i = tid; i < KNB * DF; i += THREADS) {
        int row = i >> 7, j = i & 127;
        float nf;
        if (layer == 0) {
            int id = sNid[row];
            nf = n_feat[id * DF + j] + mem_tab[id * DF + j];
        } else {
            nf = g_h1[(n * KNB + sPerm[row]) * DF + j];
        }
        sNF[row * DF + j] = nf;
        sEF[row * DF + j] = e_feat[sEid[row] * DF + j];
        sTF[row * DF + j] = fcosr(fmaf(sDt[row], freq[j], phase[j]));
    }

    // ---- P2: fused K/V GEMM: 4 rows x 24 cols per thread ----
    float acc[4][24];
#pragma unroll
    for (int rr = 0; rr < 4; rr++)
#pragma unroll
        for (int q = 0; q < 24; q++) acc[rr][q] = 0.f;

    const int rg = tid >> 5, cg = tid & 31;
    const int r0 = rg * 4;
    const int et0 = sEt[r0];
    int etr[4];
#pragma unroll
    for (int rr = 0; rr < 4; rr++) etr[rr] = sEt[r0 + rr];
    const bool uni = (et0 == sEt[r0 + 3]);

    const float* gW0 = &g_WA[layer][0][0];
    const float* gW1 = &g_WA[layer][1][0];
    const float* gW2 = &g_WB[layer][0];
    const float* gW3 = &g_WC[layer][0];

#pragma unroll 1
    for (int m0 = 0; m0 < DF; m0 += MC) {
        __syncthreads();
#pragma unroll 1
        for (int i = tid; i < 4 * MC * 192; i += THREADS) {
            int mat = i / (MC * 192);
            int rem = i - mat * (MC * 192);
            int mm = rem / 192;
            int c4 = rem - mm * 192;
            const float* src = (mat == 0) ? gW0 : (mat == 1) ? gW1 : (mat == 2) ? gW2 : gW3;
            ((float4*)sWS)[i] = ((const float4*)(src + (m0 + mm) * C2))[c4];
        }
        __syncthreads();
#pragma unroll 1
        for (int mm = 0; mm < MC; mm++) {
            const int m = m0 + mm;
            float xn[4], xe[4], xt[4];
#pragma unroll
            for (int rr = 0; rr < 4; rr++) {
                xn[rr] = sNF[(r0 + rr) * DF + m];
                xe[rr] = sEF[(r0 + rr) * DF + m];
                xt[rr] = sTF[(r0 + rr) * DF + m];
            }
            const float* wbb = sWS + (2 * MC + mm) * C2 + cg * 4;
            const float* wcc = sWS + (3 * MC + mm) * C2 + cg * 4;
            if (uni) {
                const float* waa = sWS + (et0 * MC + mm) * C2 + cg * 4;
#pragma unroll
                for (int j = 0; j < 6; j++) {
                    float4 a4 = *(const float4*)(waa + j * 128);
                    float4 b4 = *(const float4*)(wbb + j * 128);
                    float4 c4 = *(const float4*)(wcc + j * 128);
#pragma unroll
                    for (int rr = 0; rr < 4; rr++) {
                        fma4(&acc[rr][j * 4], xn[rr], a4);
                        fma4(&acc[rr][j * 4], xe[rr], b4);
                        fma4(&acc[rr][j * 4], xt[rr], c4);
                    }
                }
            } else {
#pragma unroll
                for (int j = 0; j < 6; j++) {
                    float4 b4 = *(const float4*)(wbb + j * 128);
                    float4 c4 = *(const float4*)(wcc + j * 128);
#pragma unroll
                    for (int rr = 0; rr < 4; rr++) {
                        float4 a4 = *(const float4*)(sWS + (etr[rr] * MC + mm) * C2 + cg * 4 + j * 128);
                        fma4(&acc[rr][j * 4], xn[rr], a4);
                        fma4(&acc[rr][j * 4], xe[rr], b4);
                        fma4(&acc[rr][j * 4], xt[rr], c4);
                    }
                }
            }
        }
    }
    __syncthreads();   // all reads of sWS/sNF done before KVH overlay store
#pragma unroll
    for (int rr = 0; rr < 4; rr++) {
#pragma unroll
        for (int j = 0; j < 6; j++) {
            float4 v = make_float4(acc[rr][j * 4], acc[rr][j * 4 + 1],
                                   acc[rr][j * 4 + 2], acc[rr][j * 4 + 3]);
            *(float4*)(sKVH + (r0 + rr) * KVP + cg * 4 + j * 128) = v;
        }
    }
    __syncthreads();

    // ---- P4: attention ----
    if (tid < HH * KNB) {
        int h = tid / KNB, row = tid % KNB;
        const float* kr = sKVH + row * KVP + h * DHD;
        const float* qk = sQ + h * DHD;
        float s = 0.f;
        for (int d = 0; d < DHD; d++) s = fmaf(qk[d], kr[d], s);
        s *= 0.10206207261596577f;   // 1/sqrt(96)
        if (sMask[row]) s = -1000000000.0f;
        sS[h * KNB + row] = s;
    }
    __syncthreads();
    if (tid < HH) {
        float mx = -INFINITY;
        for (int k = 0; k < KNB; k++) mx = fmaxf(mx, sS[tid * KNB + k]);
        float sum = 0.f;
        for (int k = 0; k < KNB; k++) {
            float e = expf(sS[tid * KNB + k] - mx);
            sS[tid * KNB + k] = e;
            sum += e;
        }
        float inv = 1.f / sum;
        for (int k = 0; k < KNB; k++) sS[tid * KNB + k] *= inv;
    }
    __syncthreads();
    for (int c = tid; c < MDIM; c += THREADS) {
        int h = c / DHD;
        float o = 0.f;
        for (int k = 0; k < KNB; k++)
            o = fmaf(sS[h * KNB + k], sKVH[k * KVP + MDIM + c], o);
        sO[c] = o;
    }
    __syncthreads();

    // ---- P5: output MLP (Wo fused into WoM1) ----
    if (tid < DF) {
        float a1 = bm1[layer * DF + tid];
        const float* w1 = &g_WoM1[layer][tid];
        for (int i = 0; i < MDIM; i++) a1 = fmaf(sO[i], w1[i * DF], a1);
        const float* w1b = Wm1 + (layer * 512 + MDIM) * DF + tid;
        for (int m = 0; m < DF; m++) a1 = fmaf(sSRC[m], w1b[m * DF], a1);
        sR[tid] = fmaxf(a1, 0.f);
    }
    __syncthreads();
    if (tid < DF) {
        float a2 = bm2[layer * DF + tid];
        const float* w2 = Wm2 + layer * DF * DF + tid;
        for (int d = 0; d < DF; d++) a2 = fmaf(sR[d], w2[d * DF], a2);
        float* hout = (layer == 0) ? g_h1 : g_h2;
        hout[n * DF + tid] = a2;
    }
}

// ---------------- final bilinear score + sigmoid ----------------
__global__ void final_kernel(const int* __restrict__ etype_l,
                             const float* __restrict__ Wmatch,
                             const float* __restrict__ bmatch,
                             float* __restrict__ out) {
    __shared__ float ste[128];
    __shared__ float red[128];
    int b = blockIdx.x, d = threadIdx.x;
    int et = etype_l[b];
    ste[d] = g_h2[(BB + b) * DF + d];
    __syncthreads();
    float se = g_h2[b * DF + d];
    const float* wm = Wmatch + (et * DF + d) * DF;
    float v = 0.f;
    for (int e = 0; e < DF; e++) v = fmaf(wm[e], ste[e], v);
    red[d] = se * v;
    __syncthreads();
    for (int s = 64; s > 0; s >>= 1) {
        if (d < s) red[d] += red[d + s];
        __syncthreads();
    }
    if (d == 0) {
        float score = red[0] + bmatch[et];
        out[b] = 1.f / (1.f + expf(-score));
    }
}

extern "C" void kernel_launch(void* const* d_in, const int* in_sizes, int n_in,
                              void* d_out, int out_size) {
    const int*   src_idx   = (const int*)d_in[0];
    const int*   tgt_idx   = (const int*)d_in[1];
    const float* cut_time  = (const float*)d_in[2];
    const int*   etype_l   = (const int*)d_in[5];
    const int*   ngh_node2 = (const int*)d_in[6];
    const int*   ngh_eidx2 = (const int*)d_in[7];
    const float* ngh_t2    = (const float*)d_in[8];
    const int*   ngh_et2   = (const int*)d_in[9];
    const int*   ngh_node1 = (const int*)d_in[11];
    const int*   ngh_eidx1 = (const int*)d_in[12];
    const float* ngh_t1    = (const float*)d_in[13];
    const int*   ngh_et1   = (const int*)d_in[14];
    const float* n_feat    = (const float*)d_in[16];
    const float* e_feat    = (const float*)d_in[17];
    const float* mem_tab   = (const float*)d_in[18];
    const float* freq      = (const float*)d_in[19];
    const float* phase     = (const float*)d_in[20];
    const float* Wq        = (const float*)d_in[21];
    const float* Wk        = (const float*)d_in[22];
    const float* Wv        = (const float*)d_in[23];
    const float* Wo        = (const float*)d_in[24];
    const float* Wm1       = (const float*)d_in[25];
    const float* bm1       = (const float*)d_in[26];
    const float* Wm2       = (const float*)d_in[27];
    const float* bm2       = (const float*)d_in[28];
    const float* Wrel      = (const float*)d_in[29];
    const float* Wmatch    = (const float*)d_in[30];
    const float* bmatch    = (const float*)d_in[31];
    float* out = (float*)d_out;

    const int SMEM_BYTES = 41536 * 4;   // 162.25 KB dynamic
    cudaFuncSetAttribute(attn_kernel, cudaFuncAttributeMaxDynamicSharedMemorySize, SMEM_BYTES);

    pre_weights<<<1024, 256>>>(Wrel, Wk, Wv);
    pre_misc<<<770, 384>>>(Wq, Wo, Wm1, phase);

    // layer 1: 10240 query nodes (neighbors of layer-2 neighbors)
    attn_kernel<<<N1Q, THREADS, SMEM_BYTES>>>(
        0, ngh_node1, ngh_eidx1, ngh_t1, ngh_et1,
        ngh_node2, (const int*)0, ngh_t2,
        n_feat, e_feat, mem_tab, freq, phase, Wq, Wm1, bm1, Wm2, bm2);

    // layer 2: 256 query nodes (src + tgt)
    attn_kernel<<<N2Q, THREADS, SMEM_BYTES>>>(
        1, ngh_node2, ngh_eidx2, ngh_t2, ngh_et2,
        src_idx, tgt_idx, cut_time,
        n_feat, e_feat, mem_tab, freq, phase, Wq, Wm1, bm1, Wm2, bm2);

    final_kernel<<<BB, 128>>>(etype_l, Wmatch, bmatch, out);
}

// round 4
// speedup vs baseline: 3.7527x; 3.7527x over previous
#include <cuda_runtime.h>
#include <cuda_fp16.h>
#include <math.h>
#include <stdint.h>

#define KNB 40
#define DF 128
#define MDIM 384
#define HH 4
#define DHD 96
#define BB 128
#define R1 409600
#define R2 10240
#define KX 512
#define NOUT 768
#define KVP 772
#define NPB 8

// ---------------- scratch (__device__ globals, no allocation) ----------------
__device__ __align__(16) __half g_X[(size_t)R1 * KX];          // gathered features (fp16)
__device__ __align__(16) __half g_Wt[2 * NOUT * KX];           // fused K|V weights [l][n][k]
__device__ __align__(16) float  g_KV[(size_t)R1 * NOUT];       // K|V projections (fp32)
__device__ float g_qconst[2][384];
__device__ float g_WoM1[2][384 * 128];
__device__ float g_h1[R2 * DF];
__device__ float g_h2[256 * DF];

// ---------------- helpers ----------------
__device__ __forceinline__ uint32_t smem_u32(const void* p) {
    return (uint32_t)__cvta_generic_to_shared((void*)p);
}
#define CP_ASYNC16(dst, src) \
    asm volatile("cp.async.cg.shared.global [%0], [%1], 16;" :: "r"(dst), "l"(src) : "memory")
#define CP_COMMIT() asm volatile("cp.async.commit_group;" ::: "memory")
#define CP_WAIT(n)  asm volatile("cp.async.wait_group %0;" :: "n"(n) : "memory")

__device__ __forceinline__ void mma16816(float* c, uint32_t a0, uint32_t a1,
                                         uint32_t a2, uint32_t a3,
                                         uint32_t b0, uint32_t b1) {
    asm volatile(
        "mma.sync.aligned.m16n8k16.row.col.f32.f16.f16.f32 "
        "{%0,%1,%2,%3}, {%4,%5,%6,%7}, {%8,%9}, {%0,%1,%2,%3};"
        : "+f"(c[0]), "+f"(c[1]), "+f"(c[2]), "+f"(c[3])
        : "r"(a0), "r"(a1), "r"(a2), "r"(a3), "r"(b0), "r"(b1));
}

// cos with range reduction (args up to ~2000 rad)
__device__ __forceinline__ float fcosr(float x) {
    float n = rintf(x * 0.15915494309189535f);
    float r = fmaf(n, -6.2831855f, x);
    r = fmaf(n, 1.7484556e-7f, r);
    return __cosf(r);
}

// ------------- precompute: fused transposed K|V weights (fp16) ---------------
// g_Wt[l][n][k]: n<384 -> K-proj col n; n>=384 -> V-proj col n-384.
// k blocks: [0:128)=Wrel0@W, [128:256)=Wrel1@W, [256:384)=W rows 128..255 (edge),
//           [384:512)=W rows 256..383 (time)
__global__ void pre_weights(const float* __restrict__ Wrel,
                            const float* __restrict__ Wk,
                            const float* __restrict__ Wv) {
    int l = blockIdx.x / NOUT;
    int n = blockIdx.x % NOUT;
    int t = threadIdx.x;   // 128
    const float* Ws = ((n < MDIM) ? Wk : Wv) + (size_t)l * MDIM * MDIM;
    int nc = (n < MDIM) ? n : n - MDIM;
    const float* wr0 = Wrel + ((size_t)(l * 2 + 0) * DF + t) * DF;
    const float* wr1 = Wrel + ((size_t)(l * 2 + 1) * DF + t) * DF;
    float v0 = 0.f, v1 = 0.f;
    for (int j = 0; j < DF; j++) {
        float w = Ws[(size_t)j * MDIM + nc];
        v0 = fmaf(wr0[j], w, v0);
        v1 = fmaf(wr1[j], w, v1);
    }
    size_t base = ((size_t)l * NOUT + n) * KX;
    g_Wt[base + t]        = __float2half_rn(v0);
    g_Wt[base + DF + t]   = __float2half_rn(v1);
    g_Wt[base + 256 + t]  = __float2half_rn(Ws[(size_t)(DF + t) * MDIM + nc]);
    g_Wt[base + 384 + t]  = __float2half_rn(Ws[(size_t)(256 + t) * MDIM + nc]);
}

// ---------------- precompute: qconst + Wo@Wm1 ----------------
__global__ void pre_misc(const float* __restrict__ Wq,
                         const float* __restrict__ Wo,
                         const float* __restrict__ Wm1,
                         const float* __restrict__ phase) {
    int bid = blockIdx.x;          // 770 = 2*(384+1)
    int l = bid / 385;
    int r = bid % 385;
    int tid = threadIdx.x;         // 384
    if (r == 384) {
        float acc = 0.f;
        for (int j = 0; j < 128; j++)
            acc = fmaf(cosf(phase[j]), Wq[(size_t)l * MDIM * MDIM + (256 + j) * MDIM + tid], acc);
        g_qconst[l][tid] = acc;
    } else if (tid < 128) {
        float acc = 0.f;
        for (int j = 0; j < MDIM; j++)
            acc = fmaf(Wo[(size_t)l * MDIM * MDIM + r * MDIM + j],
                       Wm1[(size_t)(l * 512 + j) * 128 + tid], acc);
        g_WoM1[l][r * 128 + tid] = acc;
    }
}

// ---------------- gather: build X rows (fp16) ----------------
__global__ void gather_kernel(int layer, const int* __restrict__ nghNode,
                              const int* __restrict__ nghEidx,
                              const float* __restrict__ nghT,
                              const int* __restrict__ nghEt,
                              const float* __restrict__ parentT,
                              const float* __restrict__ n_feat,
                              const float* __restrict__ mem_tab,
                              const float* __restrict__ e_feat,
                              const float* __restrict__ freq,
                              const float* __restrict__ phase) {
    int r = blockIdx.x;
    int j = threadIdx.x;    // 128
    int node = nghNode[r];
    int eidx = nghEidx[r];
    int et = nghEt[r];
    int p = r / KNB;
    float tq = (layer == 0) ? parentT[p] : parentT[p & (BB - 1)];
    float dt = tq - nghT[r];
    float nf = (layer == 0)
        ? n_feat[(size_t)node * DF + j] + mem_tab[(size_t)node * DF + j]
        : g_h1[(size_t)r * DF + j];
    float ef = e_feat[(size_t)eidx * DF + j];
    float tf = fcosr(fmaf(dt, freq[j], phase[j]));
    size_t base = (size_t)r * KX;
    g_X[base + j]        = __float2half_rn((et == 0) ? nf : 0.f);
    g_X[base + DF + j]   = __float2half_rn((et == 1) ? nf : 0.f);
    g_X[base + 256 + j]  = __float2half_rn(ef);
    g_X[base + 384 + j]  = __float2half_rn(tf);
}

// ---------------- HMMA GEMM: KV = X @ Wt' ----------------
// CTA tile 128x128, K=512 in 8 chunks of 64, cp.async double-buffered.
// 8 warps (4M x 2N), warp tile 32x64, mma.sync m16n8k16 fp16->fp32.
#define STR 72                         // padded smem stride in halves
#define ABYTES (128 * STR * 2)         // 18432
#define BUFB   (2 * ABYTES)            // 36864 per buffer (A + B)
__global__ __launch_bounds__(256, 2)
void gemm_kernel(int layer, int mblocks) {
    extern __shared__ char smem[];
    const uint32_t smem_base = smem_u32(smem);
    const int tid = threadIdx.x;
    const int wid = tid >> 5;
    const int lane = tid & 31;
    const int m0 = blockIdx.x * 128;
    const int n0 = blockIdx.y * 128;
    const int wm = wid >> 1;           // 0..3
    const int wn = wid & 1;            // 0..1
    const int mbase = wm * 32;
    const int nbase = wn * 64;

    const __half* gW = g_Wt + (size_t)layer * NOUT * KX;

    float acc[2][8][4];
#pragma unroll
    for (int mt = 0; mt < 2; mt++)
#pragma unroll
        for (int nt = 0; nt < 8; nt++)
#pragma unroll
            for (int q = 0; q < 4; q++) acc[mt][nt][q] = 0.f;

    // stage chunk c into buffer buf
    auto stage = [&](int buf, int c) {
        const int kb = c * 64;
        const uint32_t sbase = smem_base + buf * BUFB;
#pragma unroll
        for (int it = 0; it < 8; it++) {
            int i = tid + it * 256;                // 0..2047
            int isB = i >> 10;
            int j = i & 1023;
            int row = j >> 3, seg = j & 7;
            uint32_t dst = sbase + isB * ABYTES + (uint32_t)(row * STR + seg * 8) * 2;
            const __half* src = isB ? (gW + (size_t)(n0 + row) * KX + kb + seg * 8)
                                    : (g_X + (size_t)(m0 + row) * KX + kb + seg * 8);
            CP_ASYNC16(dst, src);
        }
        CP_COMMIT();
    };

    stage(0, 0);
    for (int c = 0; c < 8; c++) {
        if (c < 7) { stage((c + 1) & 1, c + 1); CP_WAIT(1); }
        else       { CP_WAIT(0); }
        __syncthreads();
        const __half* As = (const __half*)(smem + (c & 1) * BUFB);
        const __half* Bs = (const __half*)(smem + (c & 1) * BUFB + ABYTES);
#pragma unroll
        for (int ks = 0; ks < 4; ks++) {
            const int k0 = ks * 16 + (lane & 3) * 2;
            uint32_t bf[8][2];
#pragma unroll
            for (int nt = 0; nt < 8; nt++) {
                const __half* bp = Bs + (nbase + nt * 8 + (lane >> 2)) * STR + k0;
                bf[nt][0] = *(const uint32_t*)bp;
                bf[nt][1] = *(const uint32_t*)(bp + 8);
            }
#pragma unroll
            for (int mt = 0; mt < 2; mt++) {
                const __half* ap = As + (mbase + mt * 16 + (lane >> 2)) * STR + k0;
                uint32_t a0 = *(const uint32_t*)ap;
                uint32_t a1 = *(const uint32_t*)(ap + 8 * STR);
                uint32_t a2 = *(const uint32_t*)(ap + 8);
                uint32_t a3 = *(const uint32_t*)(ap + 8 * STR + 8);
#pragma unroll
                for (int nt = 0; nt < 8; nt++)
                    mma16816(acc[mt][nt], a0, a1, a2, a3, bf[nt][0], bf[nt][1]);
            }
        }
        __syncthreads();
    }

    // epilogue: write fp32 results
#pragma unroll
    for (int mt = 0; mt < 2; mt++) {
#pragma unroll
        for (int nt = 0; nt < 8; nt++) {
            int r = m0 + mbase + mt * 16 + (lane >> 2);
            int ccol = n0 + nbase + nt * 8 + (lane & 3) * 2;
            *(float2*)(g_KV + (size_t)r * NOUT + ccol) =
                make_float2(acc[mt][nt][0], acc[mt][nt][1]);
            *(float2*)(g_KV + (size_t)(r + 8) * NOUT + ccol) =
                make_float2(acc[mt][nt][2], acc[mt][nt][3]);
        }
    }
}

// ---------------- attention + MLP: 8 query nodes per CTA ----------------
__global__ __launch_bounds__(256, 1)
void attn_kernel(int layer, const int* __restrict__ nghNode,
                 const int* __restrict__ srcA, const int* __restrict__ srcB,
                 const float* __restrict__ n_feat, const float* __restrict__ mem_tab,
                 const float* __restrict__ Wq, const float* __restrict__ Wm1,
                 const float* __restrict__ bm1, const float* __restrict__ Wm2,
                 const float* __restrict__ bm2) {
    extern __shared__ float sm[];
    float* sKV   = sm;                       // 40*772 = 30880
    float* sSRC  = sm + 30880;               // 8*128
    float* sQ    = sm + 31904;               // 8*384
    float* sO    = sm + 34976;               // 8*384
    float* sS    = sm + 38048;               // 160
    float* sA1   = sm + 38208;               // 8*128
    int*   sMask = (int*)(sm + 39232);       // 40
    const int tid = threadIdx.x;
    const int nb = blockIdx.x;

    for (int i = tid; i < NPB * DF; i += 256) {
        int node = i >> 7, j = i & 127;
        int n = nb * NPB + node;
        int sid = (layer == 0) ? srcA[n] : ((n < BB) ? srcA[n] : srcB[n - BB]);
        sSRC[i] = n_feat[(size_t)sid * DF + j] + mem_tab[(size_t)sid * DF + j];
    }
    __syncthreads();

    // Q projection for all 8 nodes (weights loaded once, reused x8)
    {
        float acc0[NPB], acc1[NPB];
#pragma unroll
        for (int i = 0; i < NPB; i++) { acc0[i] = 0.f; acc1[i] = 0.f; }
        const float* wq = Wq + (size_t)layer * MDIM * MDIM;
        for (int m = 0; m < DF; m++) {
            float w0 = wq[(size_t)m * MDIM + tid];
            float w1 = (tid < 128) ? wq[(size_t)m * MDIM + 256 + tid] : 0.f;
#pragma unroll
            for (int i = 0; i < NPB; i++) {
                float x = sSRC[i * DF + m];
                acc0[i] = fmaf(x, w0, acc0[i]);
                acc1[i] = fmaf(x, w1, acc1[i]);
            }
        }
#pragma unroll
        for (int i = 0; i < NPB; i++) {
            sQ[i * MDIM + tid] = acc0[i] + g_qconst[layer][tid];
            if (tid < 128) sQ[i * MDIM + 256 + tid] = acc1[i] + g_qconst[layer][256 + tid];
        }
    }

    for (int i = 0; i < NPB; i++) {
        const int n = nb * NPB + i;
        __syncthreads();
        if (tid < KNB) sMask[tid] = (nghNode[n * KNB + tid] == 0) ? 1 : 0;
        for (int v = tid; v < KNB * 192; v += 256) {
            int row = v / 192, c4 = v % 192;
            *(float4*)(sKV + row * KVP + c4 * 4) =
                *(const float4*)(g_KV + (size_t)(n * KNB + row) * NOUT + c4 * 4);
        }
        __syncthreads();
        if (tid < HH * KNB) {
            int h = tid / KNB, row = tid % KNB;
            const float* kr = sKV + row * KVP + h * DHD;
            const float* qk = sQ + i * MDIM + h * DHD;
            float s = 0.f;
            for (int d = 0; d < DHD; d++) s = fmaf(qk[d], kr[d], s);
            s *= 0.10206207261596577f;   // 1/sqrt(96)
            if (sMask[row]) s = -1000000000.0f;
            sS[h * KNB + row] = s;
        }
        __syncthreads();
        if (tid < HH) {
            float mx = -INFINITY;
            for (int k = 0; k < KNB; k++) mx = fmaxf(mx, sS[tid * KNB + k]);
            float sum = 0.f;
            for (int k = 0; k < KNB; k++) {
                float e = expf(sS[tid * KNB + k] - mx);
                sS[tid * KNB + k] = e;
                sum += e;
            }
            float inv = 1.f / sum;
            for (int k = 0; k < KNB; k++) sS[tid * KNB + k] *= inv;
        }
        __syncthreads();
        for (int cc = tid; cc < MDIM; cc += 256) {
            int h = cc / DHD;
            float o = 0.f;
            for (int k = 0; k < KNB; k++)
                o = fmaf(sS[h * KNB + k], sKV[k * KVP + MDIM + cc], o);
            sO[i * MDIM + cc] = o;
        }
    }
    __syncthreads();

    // MLP layer 1 (Wo folded into WoM1): 2 thread-halves x 4 nodes each
    {
        const int half = tid >> 7, col = tid & 127;
        float a[4];
#pragma unroll
        for (int i = 0; i < 4; i++) a[i] = bm1[layer * DF + col];
        const float* w1 = &g_WoM1[layer][col];
        for (int m = 0; m < MDIM; m++) {
            float w = w1[m * DF];
#pragma unroll
            for (int i = 0; i < 4; i++)
                a[i] = fmaf(sO[(half * 4 + i) * MDIM + m], w, a[i]);
        }
        const float* w1b = Wm1 + (size_t)(layer * 512 + MDIM) * DF + col;
        for (int m = 0; m < DF; m++) {
            float w = w1b[m * DF];
#pragma unroll
            for (int i = 0; i < 4; i++)
                a[i] = fmaf(sSRC[(half * 4 + i) * DF + m], w, a[i]);
        }
#pragma unroll
        for (int i = 0; i < 4; i++) sA1[(half * 4 + i) * DF + col] = fmaxf(a[i], 0.f);
    }
    __syncthreads();
    {
        const int half = tid >> 7, col = tid & 127;
        float a[4];
#pragma unroll
        for (int i = 0; i < 4; i++) a[i] = bm2[layer * DF + col];
        const float* w2 = Wm2 + (size_t)layer * DF * DF + col;
        for (int d = 0; d < DF; d++) {
            float w = w2[d * DF];
#pragma unroll
            for (int i = 0; i < 4; i++)
                a[i] = fmaf(sA1[(half * 4 + i) * DF + d], w, a[i]);
        }
        float* hout = (layer == 0) ? g_h1 : g_h2;
#pragma unroll
        for (int i = 0; i < 4; i++)
            hout[(size_t)(nb * NPB + half * 4 + i) * DF + col] = a[i];
    }
}

// ---------------- final bilinear score + sigmoid ----------------
__global__ void final_kernel(const int* __restrict__ etype_l,
                             const float* __restrict__ Wmatch,
                             const float* __restrict__ bmatch,
                             float* __restrict__ out) {
    __shared__ float ste[128];
    __shared__ float red[128];
    int b = blockIdx.x, d = threadIdx.x;
    int et = etype_l[b];
    ste[d] = g_h2[(BB + b) * DF + d];
    __syncthreads();
    float se = g_h2[b * DF + d];
    const float* wm = Wmatch + (size_t)(et * DF + d) * DF;
    float v = 0.f;
    for (int e = 0; e < DF; e++) v = fmaf(wm[e], ste[e], v);
    red[d] = se * v;
    __syncthreads();
    for (int s = 64; s > 0; s >>= 1) {
        if (d < s) red[d] += red[d + s];
        __syncthreads();
    }
    if (d == 0) {
        float score = red[0] + bmatch[et];
        out[b] = 1.f / (1.f + expf(-score));
    }
}

extern "C" void kernel_launch(void* const* d_in, const int* in_sizes, int n_in,
                              void* d_out, int out_size) {
    const int*   src_idx   = (const int*)d_in[0];
    const int*   tgt_idx   = (const int*)d_in[1];
    const float* cut_time  = (const float*)d_in[2];
    const int*   etype_l   = (const int*)d_in[5];
    const int*   ngh_node2 = (const int*)d_in[6];
    const int*   ngh_eidx2 = (const int*)d_in[7];
    const float* ngh_t2    = (const float*)d_in[8];
    const int*   ngh_et2   = (const int*)d_in[9];
    const int*   ngh_node1 = (const int*)d_in[11];
    const int*   ngh_eidx1 = (const int*)d_in[12];
    const float* ngh_t1    = (const float*)d_in[13];
    const int*   ngh_et1   = (const int*)d_in[14];
    const float* n_feat    = (const float*)d_in[16];
    const float* e_feat    = (const float*)d_in[17];
    const float* mem_tab   = (const float*)d_in[18];
    const float* freq      = (const float*)d_in[19];
    const float* phase     = (const float*)d_in[20];
    const float* Wq        = (const float*)d_in[21];
    const float* Wk        = (const float*)d_in[22];
    const float* Wv        = (const float*)d_in[23];
    const float* Wo        = (const float*)d_in[24];
    const float* Wm1       = (const float*)d_in[25];
    const float* bm1       = (const float*)d_in[26];
    const float* Wm2       = (const float*)d_in[27];
    const float* bm2       = (const float*)d_in[28];
    const float* Wrel      = (const float*)d_in[29];
    const float* Wmatch    = (const float*)d_in[30];
    const float* bmatch    = (const float*)d_in[31];
    float* out = (float*)d_out;

    const int GEMM_SMEM = 2 * BUFB;              // 73728 B
    const int ATTN_SMEM = 39272 * 4;             // 157088 B
    cudaFuncSetAttribute(gemm_kernel, cudaFuncAttributeMaxDynamicSharedMemorySize, GEMM_SMEM);
    cudaFuncSetAttribute(attn_kernel, cudaFuncAttributeMaxDynamicSharedMemorySize, ATTN_SMEM);

    pre_weights<<<2 * NOUT, 128>>>(Wrel, Wk, Wv);
    pre_misc<<<770, 384>>>(Wq, Wo, Wm1, phase);

    // ---- layer 0: 10240 query nodes, 409600 neighbor rows ----
    gather_kernel<<<R1, 128>>>(0, ngh_node1, ngh_eidx1, ngh_t1, ngh_et1,
                               ngh_t2, n_feat, mem_tab, e_feat, freq, phase);
    gemm_kernel<<<dim3(R1 / 128, NOUT / 128), 256, GEMM_SMEM>>>(0, R1 / 128);
    attn_kernel<<<R2 / NPB, 256, ATTN_SMEM>>>(0, ngh_node1, ngh_node2, (const int*)0,
                                              n_feat, mem_tab, Wq, Wm1, bm1, Wm2, bm2);

    // ---- layer 1: 256 query nodes, 10240 neighbor rows ----
    gather_kernel<<<R2, 128>>>(1, ngh_node2, ngh_eidx2, ngh_t2, ngh_et2,
                               cut_time, n_feat, mem_tab, e_feat, freq, phase);
    gemm_kernel<<<dim3(R2 / 128, NOUT / 128), 256, GEMM_SMEM>>>(1, R2 / 128);
    attn_kernel<<<256 / NPB, 256, ATTN_SMEM>>>(1, ngh_node2, src_idx, tgt_idx,
                                               n_feat, mem_tab, Wq, Wm1, bm1, Wm2, bm2);

    final_kernel<<<BB, 128>>>(etype_l, Wmatch, bmatch, out);
}

// round 6
// speedup vs baseline: 6.2925x; 1.6768x over previous
#include <cuda_runtime.h>
#include <cuda_fp16.h>
#include <math.h>
#include <stdint.h>

#define KNB 40
#define DF 128
#define MDIM 384
#define HH 4
#define DHD 96
#define BB 128
#define R1 409600
#define R2 10240
#define KX 512
#define NOUT 768
#define KVP 772
#define NPB 8

// ---------------- scratch (__device__ globals, no allocation) ----------------
__device__ __align__(16) __half g_X[(size_t)R1 * KX];          // gathered features (fp16)
__device__ __align__(16) __half g_Wt[2 * NOUT * KX];           // fused K|V weights [l][n][k]
__device__ __align__(16) __half g_KV[(size_t)R1 * NOUT];       // K|V projections (fp16)
__device__ float g_qconst[2][384];
__device__ float g_WoM1[2][384 * 128];
__device__ float g_h1[R2 * DF];
__device__ float g_h2[256 * DF];

// ---------------- helpers ----------------
__device__ __forceinline__ uint32_t smem_u32(const void* p) {
    return (uint32_t)__cvta_generic_to_shared((void*)p);
}
#define CP_ASYNC16(dst, src) \
    asm volatile("cp.async.cg.shared.global [%0], [%1], 16;" :: "r"(dst), "l"(src) : "memory")
#define CP_COMMIT() asm volatile("cp.async.commit_group;" ::: "memory")
#define CP_WAIT(n)  asm volatile("cp.async.wait_group %0;" :: "n"(n) : "memory")
#define LDSM_X4(d0, d1, d2, d3, addr) \
    asm volatile("ldmatrix.sync.aligned.m8n8.x4.shared.b16 {%0,%1,%2,%3}, [%4];" \
        : "=r"(d0), "=r"(d1), "=r"(d2), "=r"(d3) : "r"(addr))

__device__ __forceinline__ void mma16816(float* c, uint32_t a0, uint32_t a1,
                                         uint32_t a2, uint32_t a3,
                                         uint32_t b0, uint32_t b1) {
    asm volatile(
        "mma.sync.aligned.m16n8k16.row.col.f32.f16.f16.f32 "
        "{%0,%1,%2,%3}, {%4,%5,%6,%7}, {%8,%9}, {%0,%1,%2,%3};"
        : "+f"(c[0]), "+f"(c[1]), "+f"(c[2]), "+f"(c[3])
        : "r"(a0), "r"(a1), "r"(a2), "r"(a3), "r"(b0), "r"(b1));
}

// cos with range reduction (args up to ~2000 rad)
__device__ __forceinline__ float fcosr(float x) {
    float n = rintf(x * 0.15915494309189535f);
    float r = fmaf(n, -6.2831855f, x);
    r = fmaf(n, 1.7484556e-7f, r);
    return __cosf(r);
}

// ------------- precompute: fused transposed K|V weights (fp16) ---------------
__global__ void pre_weights(const float* __restrict__ Wrel,
                            const float* __restrict__ Wk,
                            const float* __restrict__ Wv) {
    int l = blockIdx.x / NOUT;
    int n = blockIdx.x % NOUT;
    int t = threadIdx.x;   // 128
    const float* Ws = ((n < MDIM) ? Wk : Wv) + (size_t)l * MDIM * MDIM;
    int nc = (n < MDIM) ? n : n - MDIM;
    const float* wr0 = Wrel + ((size_t)(l * 2 + 0) * DF + t) * DF;
    const float* wr1 = Wrel + ((size_t)(l * 2 + 1) * DF + t) * DF;
    float v0 = 0.f, v1 = 0.f;
    for (int j = 0; j < DF; j++) {
        float w = Ws[(size_t)j * MDIM + nc];
        v0 = fmaf(wr0[j], w, v0);
        v1 = fmaf(wr1[j], w, v1);
    }
    size_t base = ((size_t)l * NOUT + n) * KX;
    g_Wt[base + t]        = __float2half_rn(v0);
    g_Wt[base + DF + t]   = __float2half_rn(v1);
    g_Wt[base + 256 + t]  = __float2half_rn(Ws[(size_t)(DF + t) * MDIM + nc]);
    g_Wt[base + 384 + t]  = __float2half_rn(Ws[(size_t)(256 + t) * MDIM + nc]);
}

// ---------------- precompute: qconst + Wo@Wm1 ----------------
__global__ void pre_misc(const float* __restrict__ Wq,
                         const float* __restrict__ Wo,
                         const float* __restrict__ Wm1,
                         const float* __restrict__ phase) {
    int bid = blockIdx.x;          // 770 = 2*(384+1)
    int l = bid / 385;
    int r = bid % 385;
    int tid = threadIdx.x;         // 384
    if (r == 384) {
        float acc = 0.f;
        for (int j = 0; j < 128; j++)
            acc = fmaf(cosf(phase[j]), Wq[(size_t)l * MDIM * MDIM + (256 + j) * MDIM + tid], acc);
        g_qconst[l][tid] = acc;
    } else if (tid < 128) {
        float acc = 0.f;
        for (int j = 0; j < MDIM; j++)
            acc = fmaf(Wo[(size_t)l * MDIM * MDIM + r * MDIM + j],
                       Wm1[(size_t)(l * 512 + j) * 128 + tid], acc);
        g_WoM1[l][r * 128 + tid] = acc;
    }
}

// ---------------- gather: build X rows (fp16) ----------------
__global__ void gather_kernel(int layer, const int* __restrict__ nghNode,
                              const int* __restrict__ nghEidx,
                              const float* __restrict__ nghT,
                              const int* __restrict__ nghEt,
                              const float* __restrict__ parentT,
                              const float* __restrict__ n_feat,
                              const float* __restrict__ mem_tab,
                              const float* __restrict__ e_feat,
                              const float* __restrict__ freq,
                              const float* __restrict__ phase) {
    int r = blockIdx.x;
    int j = threadIdx.x;    // 128
    int node = nghNode[r];
    int eidx = nghEidx[r];
    int et = nghEt[r];
    int p = r / KNB;
    float tq = (layer == 0) ? parentT[p] : parentT[p & (BB - 1)];
    float dt = tq - nghT[r];
    float nf = (layer == 0)
        ? n_feat[(size_t)node * DF + j] + mem_tab[(size_t)node * DF + j]
        : g_h1[(size_t)r * DF + j];
    float ef = e_feat[(size_t)eidx * DF + j];
    float tf = fcosr(fmaf(dt, freq[j], phase[j]));
    size_t base = (size_t)r * KX;
    g_X[base + j]        = __float2half_rn((et == 0) ? nf : 0.f);
    g_X[base + DF + j]   = __float2half_rn((et == 1) ? nf : 0.f);
    g_X[base + 256 + j]  = __float2half_rn(ef);
    g_X[base + 384 + j]  = __float2half_rn(tf);
}

// ---------------- HMMA GEMM: KV = X @ Wt' ----------------
// CTA tile 128x128, K=512 in 8 chunks of 64, cp.async double-buffered,
// ldmatrix fragment loads. 8 warps (4M x 2N), warp tile 32x64.
#define STR 72                         // padded smem stride in halves (144B rows)
#define ABYTES (128 * STR * 2)         // 18432
#define BUFB   (2 * ABYTES)            // 36864 per buffer (A + B)
__global__ __launch_bounds__(256, 2)
void gemm_kernel(int layer) {
    extern __shared__ char smem[];
    const uint32_t smem_base = smem_u32(smem);
    const int tid = threadIdx.x;
    const int wid = tid >> 5;
    const int lane = tid & 31;
    const int m0 = blockIdx.x * 128;
    const int n0 = blockIdx.y * 128;
    const int wm = wid >> 1;           // 0..3
    const int wn = wid & 1;            // 0..1
    const int mbase = wm * 32;
    const int nbase = wn * 64;

    // ldmatrix lane-address components
    const int lrow = lane & 15;                      // A: row within 16
    const int akh  = (lane >> 4) * 8;                // A: k-half select
    const int brow = (lane & 7) + ((lane >> 4) * 8); // B: row within 16
    const int bkh  = ((lane >> 3) & 1) * 8;          // B: k-half select

    const __half* gW = g_Wt + (size_t)layer * NOUT * KX;

    float acc[2][8][4];
#pragma unroll
    for (int mt = 0; mt < 2; mt++)
#pragma unroll
        for (int nt = 0; nt < 8; nt++)
#pragma unroll
            for (int q = 0; q < 4; q++) acc[mt][nt][q] = 0.f;

    auto stage = [&](int buf, int c) {
        const int kb = c * 64;
        const uint32_t sbase = smem_base + buf * BUFB;
#pragma unroll
        for (int it = 0; it < 8; it++) {
            int i = tid + it * 256;                // 0..2047
            int isB = i >> 10;
            int j = i & 1023;
            int row = j >> 3, seg = j & 7;
            uint32_t dst = sbase + isB * ABYTES + (uint32_t)(row * STR + seg * 8) * 2;
            const __half* src = isB ? (gW + (size_t)(n0 + row) * KX + kb + seg * 8)
                                    : (g_X + (size_t)(m0 + row) * KX + kb + seg * 8);
            CP_ASYNC16(dst, src);
        }
        CP_COMMIT();
    };

    stage(0, 0);
    for (int c = 0; c < 8; c++) {
        if (c < 7) { stage((c + 1) & 1, c + 1); CP_WAIT(1); }
        else       { CP_WAIT(0); }
        __syncthreads();
        const uint32_t sA = smem_base + (c & 1) * BUFB;
        const uint32_t sB = sA + ABYTES;
#pragma unroll
        for (int ks = 0; ks < 4; ks++) {
            const int k16 = ks * 16;
            uint32_t bf[8][2];
#pragma unroll
            for (int nt2 = 0; nt2 < 4; nt2++) {
                uint32_t d0, d1, d2, d3;
                uint32_t addr = sB + (uint32_t)((nbase + nt2 * 16 + brow) * STR + k16 + bkh) * 2;
                LDSM_X4(d0, d1, d2, d3, addr);
                bf[nt2 * 2][0] = d0; bf[nt2 * 2][1] = d1;
                bf[nt2 * 2 + 1][0] = d2; bf[nt2 * 2 + 1][1] = d3;
            }
#pragma unroll
            for (int mt = 0; mt < 2; mt++) {
                uint32_t a0, a1, a2, a3;
                uint32_t addr = sA + (uint32_t)((mbase + mt * 16 + lrow) * STR + k16 + akh) * 2;
                LDSM_X4(a0, a1, a2, a3, addr);
#pragma unroll
                for (int nt = 0; nt < 8; nt++)
                    mma16816(acc[mt][nt], a0, a1, a2, a3, bf[nt][0], bf[nt][1]);
            }
        }
        __syncthreads();
    }

    // epilogue: write fp16 results
#pragma unroll
    for (int mt = 0; mt < 2; mt++) {
#pragma unroll
        for (int nt = 0; nt < 8; nt++) {
            int r = m0 + mbase + mt * 16 + (lane >> 2);
            int ccol = n0 + nbase + nt * 8 + (lane & 3) * 2;
            *(__half2*)(g_KV + (size_t)r * NOUT + ccol) =
                __floats2half2_rn(acc[mt][nt][0], acc[mt][nt][1]);
            *(__half2*)(g_KV + (size_t)(r + 8) * NOUT + ccol) =
                __floats2half2_rn(acc[mt][nt][2], acc[mt][nt][3]);
        }
    }
}

// ---------------- attention + MLP: 8 query nodes per CTA ----------------
__global__ __launch_bounds__(256, 1)
void attn_kernel(int layer, const int* __restrict__ nghNode,
                 const int* __restrict__ srcA, const int* __restrict__ srcB,
                 const float* __restrict__ n_feat, const float* __restrict__ mem_tab,
                 const float* __restrict__ Wq, const float* __restrict__ Wm1,
                 const float* __restrict__ bm1, const float* __restrict__ Wm2,
                 const float* __restrict__ bm2) {
    extern __shared__ float sm[];
    float* sKV   = sm;                       // 40*772 = 30880
    float* sSRC  = sm + 30880;               // 8*128
    float* sQ    = sm + 31904;               // 8*384
    float* sO    = sm + 34976;               // 8*384
    float* sS    = sm + 38048;               // 160
    float* sA1   = sm + 38208;               // 8*128
    int*   sMask = (int*)(sm + 39232);       // 40
    const int tid = threadIdx.x;
    const int nb = blockIdx.x;

    for (int i = tid; i < NPB * DF; i += 256) {
        int node = i >> 7, j = i & 127;
        int n = nb * NPB + node;
        int sid = (layer == 0) ? srcA[n] : ((n < BB) ? srcA[n] : srcB[n - BB]);
        sSRC[i] = n_feat[(size_t)sid * DF + j] + mem_tab[(size_t)sid * DF + j];
    }
    __syncthreads();

    // Q projection for all 8 nodes (weights loaded once, reused x8)
    {
        float acc0[NPB], acc1[NPB];
#pragma unroll
        for (int i = 0; i < NPB; i++) { acc0[i] = 0.f; acc1[i] = 0.f; }
        const float* wq = Wq + (size_t)layer * MDIM * MDIM;
        for (int m = 0; m < DF; m++) {
            float w0 = wq[(size_t)m * MDIM + tid];
            float w1 = (tid < 128) ? wq[(size_t)m * MDIM + 256 + tid] : 0.f;
#pragma unroll
            for (int i = 0; i < NPB; i++) {
                float x = sSRC[i * DF + m];
                acc0[i] = fmaf(x, w0, acc0[i]);
                acc1[i] = fmaf(x, w1, acc1[i]);
            }
        }
#pragma unroll
        for (int i = 0; i < NPB; i++) {
            sQ[i * MDIM + tid] = acc0[i] + g_qconst[layer][tid];
            if (tid < 128) sQ[i * MDIM + 256 + tid] = acc1[i] + g_qconst[layer][256 + tid];
        }
    }

    for (int i = 0; i < NPB; i++) {
        const int n = nb * NPB + i;
        __syncthreads();
        if (tid < KNB) sMask[tid] = (nghNode[n * KNB + tid] == 0) ? 1 : 0;
        for (int v = tid; v < KNB * 96; v += 256) {      // 8 halves per step
            int row = v / 96, c8 = v % 96;
            uint4 pk = *(const uint4*)(g_KV + (size_t)(n * KNB + row) * NOUT + c8 * 8);
            float* dst = sKV + row * KVP + c8 * 8;
            float2 f0 = __half22float2(*(__half2*)&pk.x);
            float2 f1 = __half22float2(*(__half2*)&pk.y);
            float2 f2 = __half22float2(*(__half2*)&pk.z);
            float2 f3 = __half22float2(*(__half2*)&pk.w);
            dst[0] = f0.x; dst[1] = f0.y; dst[2] = f1.x; dst[3] = f1.y;
            dst[4] = f2.x; dst[5] = f2.y; dst[6] = f3.x; dst[7] = f3.y;
        }
        __syncthreads();
        if (tid < HH * KNB) {
            int h = tid / KNB, row = tid % KNB;
            const float* kr = sKV + row * KVP + h * DHD;
            const float* qk = sQ + i * MDIM + h * DHD;
            float s = 0.f;
            for (int d = 0; d < DHD; d++) s = fmaf(qk[d], kr[d], s);
            s *= 0.10206207261596577f;   // 1/sqrt(96)
            if (sMask[row]) s = -1000000000.0f;
            sS[h * KNB + row] = s;
        }
        __syncthreads();
        if (tid < HH) {
            float mx = -INFINITY;
            for (int k = 0; k < KNB; k++) mx = fmaxf(mx, sS[tid * KNB + k]);
            float sum = 0.f;
            for (int k = 0; k < KNB; k++) {
                float e = expf(sS[tid * KNB + k] - mx);
                sS[tid * KNB + k] = e;
                sum += e;
            }
            float inv = 1.f / sum;
            for (int k = 0; k < KNB; k++) sS[tid * KNB + k] *= inv;
        }
        __syncthreads();
        for (int cc = tid; cc < MDIM; cc += 256) {
            int h = cc / DHD;
            float o = 0.f;
            for (int k = 0; k < KNB; k++)
                o = fmaf(sS[h * KNB + k], sKV[k * KVP + MDIM + cc], o);
            sO[i * MDIM + cc] = o;
        }
    }
    __syncthreads();

    // MLP layer 1 (Wo folded into WoM1): 2 thread-halves x 4 nodes each
    {
        const int half = tid >> 7, col = tid & 127;
        float a[4];
#pragma unroll
        for (int i = 0; i < 4; i++) a[i] = bm1[layer * DF + col];
        const float* w1 = &g_WoM1[layer][col];
        for (int m = 0; m < MDIM; m++) {
            float w = w1[m * DF];
#pragma unroll
            for (int i = 0; i < 4; i++)
                a[i] = fmaf(sO[(half * 4 + i) * MDIM + m], w, a[i]);
        }
        const float* w1b = Wm1 + (size_t)(layer * 512 + MDIM) * DF + col;
        for (int m = 0; m < DF; m++) {
            float w = w1b[m * DF];
#pragma unroll
            for (int i = 0; i < 4; i++)
                a[i] = fmaf(sSRC[(half * 4 + i) * DF + m], w, a[i]);
        }
#pragma unroll
        for (int i = 0; i < 4; i++) sA1[(half * 4 + i) * DF + col] = fmaxf(a[i], 0.f);
    }
    __syncthreads();
    {
        const int half = tid >> 7, col = tid & 127;
        float a[4];
#pragma unroll
        for (int i = 0; i < 4; i++) a[i] = bm2[layer * DF + col];
        const float* w2 = Wm2 + (size_t)layer * DF * DF + col;
        for (int d = 0; d < DF; d++) {
            float w = w2[d * DF];
#pragma unroll
            for (int i = 0; i < 4; i++)
                a[i] = fmaf(sA1[(half * 4 + i) * DF + d], w, a[i]);
        }
        float* hout = (layer == 0) ? g_h1 : g_h2;
#pragma unroll
        for (int i = 0; i < 4; i++)
            hout[(size_t)(nb * NPB + half * 4 + i) * DF + col] = a[i];
    }
}

// ---------------- final bilinear score + sigmoid ----------------
__global__ void final_kernel(const int* __restrict__ etype_l,
                             const float* __restrict__ Wmatch,
                             const float* __restrict__ bmatch,
                             float* __restrict__ out) {
    __shared__ float ste[128];
    __shared__ float red[128];
    int b = blockIdx.x, d = threadIdx.x;
    int et = etype_l[b];
    ste[d] = g_h2[(BB + b) * DF + d];
    __syncthreads();
    float se = g_h2[b * DF + d];
    const float* wm = Wmatch + (size_t)(et * DF + d) * DF;
    float v = 0.f;
    for (int e = 0; e < DF; e++) v = fmaf(wm[e], ste[e], v);
    red[d] = se * v;
    __syncthreads();
    for (int s = 64; s > 0; s >>= 1) {
        if (d < s) red[d] += red[d + s];
        __syncthreads();
    }
    if (d == 0) {
        float score = red[0] + bmatch[et];
        out[b] = 1.f / (1.f + expf(-score));
    }
}

extern "C" void kernel_launch(void* const* d_in, const int* in_sizes, int n_in,
                              void* d_out, int out_size) {
    const int*   src_idx   = (const int*)d_in[0];
    const int*   tgt_idx   = (const int*)d_in[1];
    const float* cut_time  = (const float*)d_in[2];
    const int*   etype_l   = (const int*)d_in[5];
    const int*   ngh_node2 = (const int*)d_in[6];
    const int*   ngh_eidx2 = (const int*)d_in[7];
    const float* ngh_t2    = (const float*)d_in[8];
    const int*   ngh_et2   = (const int*)d_in[9];
    const int*   ngh_node1 = (const int*)d_in[11];
    const int*   ngh_eidx1 = (const int*)d_in[12];
    const float* ngh_t1    = (const float*)d_in[13];
    const int*   ngh_et1   = (const int*)d_in[14];
    const float* n_feat    = (const float*)d_in[16];
    const float* e_feat    = (const float*)d_in[17];
    const float* mem_tab   = (const float*)d_in[18];
    const float* freq      = (const float*)d_in[19];
    const float* phase     = (const float*)d_in[20];
    const float* Wq        = (const float*)d_in[21];
    const float* Wk        = (const float*)d_in[22];
    const float* Wv        = (const float*)d_in[23];
    const float* Wo        = (const float*)d_in[24];
    const float* Wm1       = (const float*)d_in[25];
    const float* bm1       = (const float*)d_in[26];
    const float* Wm2       = (const float*)d_in[27];
    const float* bm2       = (const float*)d_in[28];
    const float* Wrel      = (const float*)d_in[29];
    const float* Wmatch    = (const float*)d_in[30];
    const float* bmatch    = (const float*)d_in[31];
    float* out = (float*)d_out;

    const int GEMM_SMEM = 2 * BUFB;              // 73728 B
    const int ATTN_SMEM = 39272 * 4;             // 157088 B
    cudaFuncSetAttribute(gemm_kernel, cudaFuncAttributeMaxDynamicSharedMemorySize, GEMM_SMEM);
    cudaFuncSetAttribute(attn_kernel, cudaFuncAttributeMaxDynamicSharedMemorySize, ATTN_SMEM);

    pre_weights<<<2 * NOUT, 128>>>(Wrel, Wk, Wv);
    pre_misc<<<770, 384>>>(Wq, Wo, Wm1, phase);

    // ---- layer 0: 10240 query nodes, 409600 neighbor rows ----
    gather_kernel<<<R1, 128>>>(0, ngh_node1, ngh_eidx1, ngh_t1, ngh_et1,
                               ngh_t2, n_feat, mem_tab, e_feat, freq, phase);
    gemm_kernel<<<dim3(R1 / 128, NOUT / 128), 256, GEMM_SMEM>>>(0);
    attn_kernel<<<R2 / NPB, 256, ATTN_SMEM>>>(0, ngh_node1, ngh_node2, (const int*)0,
                                              n_feat, mem_tab, Wq, Wm1, bm1, Wm2, bm2);

    // ---- layer 1: 256 query nodes, 10240 neighbor rows ----
    gather_kernel<<<R2, 128>>>(1, ngh_node2, ngh_eidx2, ngh_t2, ngh_et2,
                               cut_time, n_feat, mem_tab, e_feat, freq, phase);
    gemm_kernel<<<dim3(R2 / 128, NOUT / 128), 256, GEMM_SMEM>>>(1);
    attn_kernel<<<256 / NPB, 256, ATTN_SMEM>>>(1, ngh_node2, src_idx, tgt_idx,
                                               n_feat, mem_tab, Wq, Wm1, bm1, Wm2, bm2);

    final_kernel<<<BB, 128>>>(etype_l, Wmatch, bmatch, out);
}

// round 7
// speedup vs baseline: 6.9093x; 1.0980x over previous
#include <cuda_runtime.h>
#include <cuda_fp16.h>
#include <math.h>
#include <stdint.h>

#define KNB 40
#define DF 128
#define MDIM 384
#define HH 4
#define DHD 96
#define BB 128
#define R1 409600
#define R2 10240
#define KX 512
#define NOUT 768
#define NPB 8
#define KV2 776              // padded halves per KV row in smem
#define KVBUFH (KNB * KV2)   // 31040 halves per buffer

// ---------------- scratch (__device__ globals, no allocation) ----------------
__device__ __align__(16) __half g_X[(size_t)R1 * KX];          // gathered features (fp16)
__device__ __align__(16) __half g_Wt[2 * NOUT * KX];           // fused K|V weights [l][n][k]
__device__ __align__(16) __half g_KV[(size_t)R1 * NOUT];       // K|V projections (fp16)
__device__ float g_qconst[2][384];
__device__ float g_WoM1[2][384 * 128];
__device__ float g_h1[R2 * DF];
__device__ float g_h2[256 * DF];

// ---------------- helpers ----------------
__device__ __forceinline__ uint32_t smem_u32(const void* p) {
    return (uint32_t)__cvta_generic_to_shared((void*)p);
}
#define CP_ASYNC16(dst, src) \
    asm volatile("cp.async.cg.shared.global [%0], [%1], 16;" :: "r"(dst), "l"(src) : "memory")
#define CP_COMMIT() asm volatile("cp.async.commit_group;" ::: "memory")
#define CP_WAIT(n)  asm volatile("cp.async.wait_group %0;" :: "n"(n) : "memory")
#define LDSM_X4(d0, d1, d2, d3, addr) \
    asm volatile("ldmatrix.sync.aligned.m8n8.x4.shared.b16 {%0,%1,%2,%3}, [%4];" \
        : "=r"(d0), "=r"(d1), "=r"(d2), "=r"(d3) : "r"(addr))

__device__ __forceinline__ void mma16816(float* c, uint32_t a0, uint32_t a1,
                                         uint32_t a2, uint32_t a3,
                                         uint32_t b0, uint32_t b1) {
    asm volatile(
        "mma.sync.aligned.m16n8k16.row.col.f32.f16.f16.f32 "
        "{%0,%1,%2,%3}, {%4,%5,%6,%7}, {%8,%9}, {%0,%1,%2,%3};"
        : "+f"(c[0]), "+f"(c[1]), "+f"(c[2]), "+f"(c[3])
        : "r"(a0), "r"(a1), "r"(a2), "r"(a3), "r"(b0), "r"(b1));
}

// cos with range reduction (args up to ~2000 rad)
__device__ __forceinline__ float fcosr(float x) {
    float n = rintf(x * 0.15915494309189535f);
    float r = fmaf(n, -6.2831855f, x);
    r = fmaf(n, 1.7484556e-7f, r);
    return __cosf(r);
}

// ------------- precompute: fused transposed K|V weights (fp16) ---------------
__global__ void pre_weights(const float* __restrict__ Wrel,
                            const float* __restrict__ Wk,
                            const float* __restrict__ Wv) {
    int l = blockIdx.x / NOUT;
    int n = blockIdx.x % NOUT;
    int t = threadIdx.x;   // 128
    const float* Ws = ((n < MDIM) ? Wk : Wv) + (size_t)l * MDIM * MDIM;
    int nc = (n < MDIM) ? n : n - MDIM;
    const float* wr0 = Wrel + ((size_t)(l * 2 + 0) * DF + t) * DF;
    const float* wr1 = Wrel + ((size_t)(l * 2 + 1) * DF + t) * DF;
    float v0 = 0.f, v1 = 0.f;
    for (int j = 0; j < DF; j++) {
        float w = Ws[(size_t)j * MDIM + nc];
        v0 = fmaf(wr0[j], w, v0);
        v1 = fmaf(wr1[j], w, v1);
    }
    size_t base = ((size_t)l * NOUT + n) * KX;
    g_Wt[base + t]        = __float2half_rn(v0);
    g_Wt[base + DF + t]   = __float2half_rn(v1);
    g_Wt[base + 256 + t]  = __float2half_rn(Ws[(size_t)(DF + t) * MDIM + nc]);
    g_Wt[base + 384 + t]  = __float2half_rn(Ws[(size_t)(256 + t) * MDIM + nc]);
}

// ---------------- precompute: qconst + Wo@Wm1 ----------------
__global__ void pre_misc(const float* __restrict__ Wq,
                         const float* __restrict__ Wo,
                         const float* __restrict__ Wm1,
                         const float* __restrict__ phase) {
    int bid = blockIdx.x;          // 770 = 2*(384+1)
    int l = bid / 385;
    int r = bid % 385;
    int tid = threadIdx.x;         // 384
    if (r == 384) {
        float acc = 0.f;
        for (int j = 0; j < 128; j++)
            acc = fmaf(cosf(phase[j]), Wq[(size_t)l * MDIM * MDIM + (256 + j) * MDIM + tid], acc);
        g_qconst[l][tid] = acc;
    } else if (tid < 128) {
        float acc = 0.f;
        for (int j = 0; j < MDIM; j++)
            acc = fmaf(Wo[(size_t)l * MDIM * MDIM + r * MDIM + j],
                       Wm1[(size_t)(l * 512 + j) * 128 + tid], acc);
        g_WoM1[l][r * 128 + tid] = acc;
    }
}

// ---------------- gather: build X rows (fp16), 4 rows per CTA ----------------
__global__ void gather_kernel(int layer, const int* __restrict__ nghNode,
                              const int* __restrict__ nghEidx,
                              const float* __restrict__ nghT,
                              const int* __restrict__ nghEt,
                              const float* __restrict__ parentT,
                              const float* __restrict__ n_feat,
                              const float* __restrict__ mem_tab,
                              const float* __restrict__ e_feat,
                              const float* __restrict__ freq,
                              const float* __restrict__ phase) {
    int r = blockIdx.x * 4 + (threadIdx.x >> 7);
    int j = threadIdx.x & 127;
    int node = nghNode[r];
    int eidx = nghEidx[r];
    int et = nghEt[r];
    int p = r / KNB;
    float tq = (layer == 0) ? parentT[p] : parentT[p & (BB - 1)];
    float dt = tq - nghT[r];
    float nf = (layer == 0)
        ? n_feat[(size_t)node * DF + j] + mem_tab[(size_t)node * DF + j]
        : g_h1[(size_t)r * DF + j];
    float ef = e_feat[(size_t)eidx * DF + j];
    float tf = fcosr(fmaf(dt, freq[j], phase[j]));
    size_t base = (size_t)r * KX;
    g_X[base + j]        = __float2half_rn((et == 0) ? nf : 0.f);
    g_X[base + DF + j]   = __float2half_rn((et == 1) ? nf : 0.f);
    g_X[base + 256 + j]  = __float2half_rn(ef);
    g_X[base + 384 + j]  = __float2half_rn(tf);
}

// ---------------- HMMA GEMM: KV = X @ Wt' ----------------
// CTA tile 128x128, K=512 in 8 chunks of 64, cp.async 3-stage pipeline,
// ldmatrix fragment loads. 8 warps (4M x 2N), warp tile 32x64.
// Grid: (N-blocks, M-blocks) -> N fastest so X tiles hit L2 across N sweep.
#define STR 72                         // padded smem stride in halves (144B rows)
#define ABYTES (128 * STR * 2)         // 18432
#define BUFB   (2 * ABYTES)            // 36864 per stage (A + B)
__global__ __launch_bounds__(256, 2)
void gemm_kernel(int layer) {
    extern __shared__ char smem[];
    const uint32_t smem_base = smem_u32(smem);
    const int tid = threadIdx.x;
    const int wid = tid >> 5;
    const int lane = tid & 31;
    const int n0 = blockIdx.x * 128;
    const int m0 = blockIdx.y * 128;
    const int wm = wid >> 1;           // 0..3
    const int wn = wid & 1;            // 0..1
    const int mbase = wm * 32;
    const int nbase = wn * 64;

    const int lrow = lane & 15;                      // A: row within 16
    const int akh  = (lane >> 4) * 8;                // A: k-half select
    const int brow = (lane & 7) + ((lane >> 4) * 8); // B: row within 16
    const int bkh  = ((lane >> 3) & 1) * 8;          // B: k-half select

    const __half* gW = g_Wt + (size_t)layer * NOUT * KX;

    float acc[2][8][4];
#pragma unroll
    for (int mt = 0; mt < 2; mt++)
#pragma unroll
        for (int nt = 0; nt < 8; nt++)
#pragma unroll
            for (int q = 0; q < 4; q++) acc[mt][nt][q] = 0.f;

    auto stage = [&](int c) {
        const int kb = c * 64;
        const uint32_t sbase = smem_base + (c % 3) * BUFB;
#pragma unroll
        for (int it = 0; it < 8; it++) {
            int i = tid + it * 256;                // 0..2047
            int isB = i >> 10;
            int j = i & 1023;
            int row = j >> 3, seg = j & 7;
            uint32_t dst = sbase + isB * ABYTES + (uint32_t)(row * STR + seg * 8) * 2;
            const __half* src = isB ? (gW + (size_t)(n0 + row) * KX + kb + seg * 8)
                                    : (g_X + (size_t)(m0 + row) * KX + kb + seg * 8);
            CP_ASYNC16(dst, src);
        }
        CP_COMMIT();
    };

    stage(0);
    stage(1);
    for (int c = 0; c < 8; c++) {
        if (c < 7) CP_WAIT(1); else CP_WAIT(0);
        __syncthreads();
        const uint32_t sA = smem_base + (c % 3) * BUFB;
        const uint32_t sB = sA + ABYTES;
#pragma unroll
        for (int ks = 0; ks < 4; ks++) {
            const int k16 = ks * 16;
            uint32_t bf[8][2];
#pragma unroll
            for (int nt2 = 0; nt2 < 4; nt2++) {
                uint32_t d0, d1, d2, d3;
                uint32_t addr = sB + (uint32_t)((nbase + nt2 * 16 + brow) * STR + k16 + bkh) * 2;
                LDSM_X4(d0, d1, d2, d3, addr);
                bf[nt2 * 2][0] = d0; bf[nt2 * 2][1] = d1;
                bf[nt2 * 2 + 1][0] = d2; bf[nt2 * 2 + 1][1] = d3;
            }
#pragma unroll
            for (int mt = 0; mt < 2; mt++) {
                uint32_t a0, a1, a2, a3;
                uint32_t addr = sA + (uint32_t)((mbase + mt * 16 + lrow) * STR + k16 + akh) * 2;
                LDSM_X4(a0, a1, a2, a3, addr);
#pragma unroll
                for (int nt = 0; nt < 8; nt++)
                    mma16816(acc[mt][nt], a0, a1, a2, a3, bf[nt][0], bf[nt][1]);
            }
        }
        __syncthreads();
        if (c + 2 < 8) stage(c + 2);
    }

    // epilogue: write fp16 results
#pragma unroll
    for (int mt = 0; mt < 2; mt++) {
#pragma unroll
        for (int nt = 0; nt < 8; nt++) {
            int r = m0 + mbase + mt * 16 + (lane >> 2);
            int ccol = n0 + nbase + nt * 8 + (lane & 3) * 2;
            *(__half2*)(g_KV + (size_t)r * NOUT + ccol) =
                __floats2half2_rn(acc[mt][nt][0], acc[mt][nt][1]);
            *(__half2*)(g_KV + (size_t)(r + 8) * NOUT + ccol) =
                __floats2half2_rn(acc[mt][nt][2], acc[mt][nt][3]);
        }
    }
}

// ---------------- attention + MLP: 8 query nodes per CTA ----------------
// KV double-buffered in smem as fp16 via cp.async; warp-parallel softmax.
__global__ __launch_bounds__(256, 1)
void attn_kernel(int layer, const int* __restrict__ nghNode,
                 const int* __restrict__ srcA, const int* __restrict__ srcB,
                 const float* __restrict__ n_feat, const float* __restrict__ mem_tab,
                 const float* __restrict__ Wq, const float* __restrict__ Wm1,
                 const float* __restrict__ bm1, const float* __restrict__ Wm2,
                 const float* __restrict__ bm2) {
    extern __shared__ float sm[];
    __half* sKVh = (__half*)sm;              // 2 x 31040 halves = 31040 floats
    float* sSRC  = sm + 31040;               // 8*128
    float* sQ    = sm + 32064;               // 8*384
    float* sO    = sm + 35136;               // 8*384
    float* sS    = sm + 38208;               // 160
    float* sA1   = sm + 38368;               // 8*128
    int*   sMask = (int*)(sm + 39392);       // 40  (end 39432 floats)
    const int tid = threadIdx.x;
    const int nb = blockIdx.x;
    const uint32_t smem_base = smem_u32(sm);

    for (int i = tid; i < NPB * DF; i += 256) {
        int node = i >> 7, j = i & 127;
        int n = nb * NPB + node;
        int sid = (layer == 0) ? srcA[n] : ((n < BB) ? srcA[n] : srcB[n - BB]);
        sSRC[i] = n_feat[(size_t)sid * DF + j] + mem_tab[(size_t)sid * DF + j];
    }

    auto stageKV = [&](int i, int buf) {
        const __half* src = g_KV + (size_t)(nb * NPB + i) * KNB * NOUT;
        const uint32_t dbase = smem_base + buf * (KVBUFH * 2);
        for (int v = tid; v < KNB * 96; v += 256) {
            int row = v / 96, c8 = v % 96;
            CP_ASYNC16(dbase + (uint32_t)(row * KV2 + c8 * 8) * 2,
                       src + (size_t)row * NOUT + c8 * 8);
        }
        CP_COMMIT();
    };
    stageKV(0, 0);
    __syncthreads();

    // Q projection for all 8 nodes (weights loaded once, reused x8)
    {
        float acc0[NPB], acc1[NPB];
#pragma unroll
        for (int i = 0; i < NPB; i++) { acc0[i] = 0.f; acc1[i] = 0.f; }
        const float* wq = Wq + (size_t)layer * MDIM * MDIM;
        for (int m = 0; m < DF; m++) {
            float w0 = wq[(size_t)m * MDIM + tid];
            float w1 = (tid < 128) ? wq[(size_t)m * MDIM + 256 + tid] : 0.f;
#pragma unroll
            for (int i = 0; i < NPB; i++) {
                float x = sSRC[i * DF + m];
                acc0[i] = fmaf(x, w0, acc0[i]);
                acc1[i] = fmaf(x, w1, acc1[i]);
            }
        }
#pragma unroll
        for (int i = 0; i < NPB; i++) {
            sQ[i * MDIM + tid] = acc0[i] + g_qconst[layer][tid];
            if (tid < 128) sQ[i * MDIM + 256 + tid] = acc1[i] + g_qconst[layer][256 + tid];
        }
    }

    for (int i = 0; i < NPB; i++) {
        const int n = nb * NPB + i;
        if (i < 7) stageKV(i + 1, (i + 1) & 1);
        if (tid < KNB) sMask[tid] = (nghNode[n * KNB + tid] == 0) ? 1 : 0;
        if (i < 7) CP_WAIT(1); else CP_WAIT(0);
        __syncthreads();
        const __half* kvb = sKVh + (i & 1) * KVBUFH;
        // scores
        if (tid < HH * KNB) {
            int h = tid / KNB, row = tid % KNB;
            const __half2* kr2 = (const __half2*)(kvb + row * KV2 + h * DHD);
            const float* qk = sQ + i * MDIM + h * DHD;
            float s = 0.f;
#pragma unroll
            for (int d2 = 0; d2 < DHD / 2; d2++) {
                float2 kf = __half22float2(kr2[d2]);
                s = fmaf(qk[2 * d2], kf.x, s);
                s = fmaf(qk[2 * d2 + 1], kf.y, s);
            }
            s *= 0.10206207261596577f;   // 1/sqrt(96)
            if (sMask[row]) s = -1000000000.0f;
            sS[h * KNB + row] = s;
        }
        __syncthreads();
        // warp-parallel softmax: warp h handles head h
        if (tid < 128) {
            int h = tid >> 5, lane = tid & 31;
            float v0 = sS[h * KNB + lane];
            float v1 = (lane < 8) ? sS[h * KNB + 32 + lane] : -INFINITY;
            float mx = fmaxf(v0, v1);
#pragma unroll
            for (int o = 16; o > 0; o >>= 1)
                mx = fmaxf(mx, __shfl_xor_sync(0xFFFFFFFF, mx, o));
            float e0 = expf(v0 - mx);
            float e1 = (lane < 8) ? expf(v1 - mx) : 0.f;
            float sum = e0 + e1;
#pragma unroll
            for (int o = 16; o > 0; o >>= 1)
                sum += __shfl_xor_sync(0xFFFFFFFF, sum, o);
            float inv = 1.f / sum;
            sS[h * KNB + lane] = e0 * inv;
            if (lane < 8) sS[h * KNB + 32 + lane] = e1 * inv;
        }
        __syncthreads();
        // o = a @ V
        for (int cc = tid; cc < MDIM; cc += 256) {
            int h = cc / DHD;
            const float* a = sS + h * KNB;
            float o = 0.f;
            for (int k = 0; k < KNB; k++)
                o = fmaf(a[k], __half2float(kvb[k * KV2 + MDIM + cc]), o);
            sO[i * MDIM + cc] = o;
        }
        __syncthreads();
    }

    // MLP layer 1 (Wo folded into WoM1): 2 thread-halves x 4 nodes each
    {
        const int half = tid >> 7, col = tid & 127;
        float a[4];
#pragma unroll
        for (int i = 0; i < 4; i++) a[i] = bm1[layer * DF + col];
        const float* w1 = &g_WoM1[layer][col];
        for (int m = 0; m < MDIM; m++) {
            float w = w1[m * DF];
#pragma unroll
            for (int i = 0; i < 4; i++)
                a[i] = fmaf(sO[(half * 4 + i) * MDIM + m], w, a[i]);
        }
        const float* w1b = Wm1 + (size_t)(layer * 512 + MDIM) * DF + col;
        for (int m = 0; m < DF; m++) {
            float w = w1b[m * DF];
#pragma unroll
            for (int i = 0; i < 4; i++)
                a[i] = fmaf(sSRC[(half * 4 + i) * DF + m], w, a[i]);
        }
#pragma unroll
        for (int i = 0; i < 4; i++) sA1[(half * 4 + i) * DF + col] = fmaxf(a[i], 0.f);
    }
    __syncthreads();
    {
        const int half = tid >> 7, col = tid & 127;
        float a[4];
#pragma unroll
        for (int i = 0; i < 4; i++) a[i] = bm2[layer * DF + col];
        const float* w2 = Wm2 + (size_t)layer * DF * DF + col;
        for (int d = 0; d < DF; d++) {
            float w = w2[d * DF];
#pragma unroll
            for (int i = 0; i < 4; i++)
                a[i] = fmaf(sA1[(half * 4 + i) * DF + d], w, a[i]);
        }
        float* hout = (layer == 0) ? g_h1 : g_h2;
#pragma unroll
        for (int i = 0; i < 4; i++)
            hout[(size_t)(nb * NPB + half * 4 + i) * DF + col] = a[i];
    }
}

// ---------------- final bilinear score + sigmoid ----------------
__global__ void final_kernel(const int* __restrict__ etype_l,
                             const float* __restrict__ Wmatch,
                             const float* __restrict__ bmatch,
                             float* __restrict__ out) {
    __shared__ float ste[128];
    __shared__ float red[128];
    int b = blockIdx.x, d = threadIdx.x;
    int et = etype_l[b];
    ste[d] = g_h2[(BB + b) * DF + d];
    __syncthreads();
    float se = g_h2[b * DF + d];
    const float* wm = Wmatch + (size_t)(et * DF + d) * DF;
    float v = 0.f;
    for (int e = 0; e < DF; e++) v = fmaf(wm[e], ste[e], v);
    red[d] = se * v;
    __syncthreads();
    for (int s = 64; s > 0; s >>= 1) {
        if (d < s) red[d] += red[d + s];
        __syncthreads();
    }
    if (d == 0) {
        float score = red[0] + bmatch[et];
        out[b] = 1.f / (1.f + expf(-score));
    }
}

extern "C" void kernel_launch(void* const* d_in, const int* in_sizes, int n_in,
                              void* d_out, int out_size) {
    const int*   src_idx   = (const int*)d_in[0];
    const int*   tgt_idx   = (const int*)d_in[1];
    const float* cut_time  = (const float*)d_in[2];
    const int*   etype_l   = (const int*)d_in[5];
    const int*   ngh_node2 = (const int*)d_in[6];
    const int*   ngh_eidx2 = (const int*)d_in[7];
    const float* ngh_t2    = (const float*)d_in[8];
    const int*   ngh_et2   = (const int*)d_in[9];
    const int*   ngh_node1 = (const int*)d_in[11];
    const int*   ngh_eidx1 = (const int*)d_in[12];
    const float* ngh_t1    = (const float*)d_in[13];
    const int*   ngh_et1   = (const int*)d_in[14];
    const float* n_feat    = (const float*)d_in[16];
    const float* e_feat    = (const float*)d_in[17];
    const float* mem_tab   = (const float*)d_in[18];
    const float* freq      = (const float*)d_in[19];
    const float* phase     = (const float*)d_in[20];
    const float* Wq        = (const float*)d_in[21];
    const float* Wk        = (const float*)d_in[22];
    const float* Wv        = (const float*)d_in[23];
    const float* Wo        = (const float*)d_in[24];
    const float* Wm1       = (const float*)d_in[25];
    const float* bm1       = (const float*)d_in[26];
    const float* Wm2       = (const float*)d_in[27];
    const float* bm2       = (const float*)d_in[28];
    const float* Wrel      = (const float*)d_in[29];
    const float* Wmatch    = (const float*)d_in[30];
    const float* bmatch    = (const float*)d_in[31];
    float* out = (float*)d_out;

    const int GEMM_SMEM = 3 * BUFB;              // 110592 B
    const int ATTN_SMEM = 39432 * 4;             // 157728 B
    cudaFuncSetAttribute(gemm_kernel, cudaFuncAttributeMaxDynamicSharedMemorySize, GEMM_SMEM);
    cudaFuncSetAttribute(attn_kernel, cudaFuncAttributeMaxDynamicSharedMemorySize, ATTN_SMEM);

    pre_weights<<<2 * NOUT, 128>>>(Wrel, Wk, Wv);
    pre_misc<<<770, 384>>>(Wq, Wo, Wm1, phase);

    // ---- layer 0: 10240 query nodes, 409600 neighbor rows ----
    gather_kernel<<<R1 / 4, 512>>>(0, ngh_node1, ngh_eidx1, ngh_t1, ngh_et1,
                                   ngh_t2, n_feat, mem_tab, e_feat, freq, phase);
    gemm_kernel<<<dim3(NOUT / 128, R1 / 128), 256, GEMM_SMEM>>>(0);
    attn_kernel<<<R2 / NPB, 256, ATTN_SMEM>>>(0, ngh_node1, ngh_node2, (const int*)0,
                                              n_feat, mem_tab, Wq, Wm1, bm1, Wm2, bm2);

    // ---- layer 1: 256 query nodes, 10240 neighbor rows ----
    gather_kernel<<<R2 / 4, 512>>>(1, ngh_node2, ngh_eidx2, ngh_t2, ngh_et2,
                                   cut_time, n_feat, mem_tab, e_feat, freq, phase);
    gemm_kernel<<<dim3(NOUT / 128, R2 / 128), 256, GEMM_SMEM>>>(1);
    attn_kernel<<<256 / NPB, 256, ATTN_SMEM>>>(1, ngh_node2, src_idx, tgt_idx,
                                               n_feat, mem_tab, Wq, Wm1, bm1, Wm2, bm2);

    final_kernel<<<BB, 128>>>(etype_l, Wmatch, bmatch, out);
}